// round 2
// baseline (speedup 1.0000x reference)
#include <cuda_runtime.h>
#include <cuda_bf16.h>
#include <math.h>

#define NN 50000
#define FF 96
#define MM 128
#define EE 800000

// ---------------- scratch (device globals; no allocation allowed) ----------
__device__ float g_xemb[NN * FF];   // x_embed
__device__ float g_agg[NN * FF];    // scatter sum
__device__ float g_deg[NN];         // degree
__device__ float g_sum[FF];         // BN sum
__device__ float g_sq[FF];          // BN sum of squares

// ---------------- kernel 0: zero scratch ----------------
__global__ void k_zero(int nAgg, int nDeg) {
    int idx = blockIdx.x * blockDim.x + threadIdx.x;
    int stride = gridDim.x * blockDim.x;
    for (int i = idx; i < nAgg; i += stride) g_agg[i] = 0.f;
    for (int i = idx; i < nDeg; i += stride) g_deg[i] = 0.f;
    if (idx < FF) { g_sum[idx] = 0.f; g_sq[idx] = 0.f; }
}

// ---------------- kernel 1: Fourier embed + projection ----------------
// x[N,3] -> angles[N,128] -> [cos|sin][N,256] @ W_proj[256,96] + b -> g_xemb
#define TN 64
#define FSTR 266   // smem row stride for ffm tile

__global__ __launch_bounds__(256) void k_embed(
    const float* __restrict__ x, const float* __restrict__ B,
    const float* __restrict__ Wp, const float* __restrict__ bp, int nNodes)
{
    extern __shared__ float sm[];
    float* sW = sm;                    // 256*96
    float* sF = sm + 256 * 96;         // TN*FSTR
    __shared__ float sx[TN][3];
    __shared__ float sB[3 * 128];

    const int t = threadIdx.x;
    const int n0 = blockIdx.x * TN;

    for (int i = t; i < 256 * 96; i += 256) sW[i] = Wp[i];
    for (int i = t; i < 3 * 128; i += 256) sB[i] = B[i];
    for (int i = t; i < TN * 3; i += 256) {
        int n = n0 + i / 3;
        sx[i / 3][i % 3] = (n < nNodes) ? x[n * 3 + (i % 3)] : 0.f;
    }
    __syncthreads();

    const float TWO_PI = 6.283185307179586f;
    for (int i = t; i < TN * 128; i += 256) {
        int n = i >> 7, m = i & 127;
        float a = sx[n][0] * sB[m] + sx[n][1] * sB[128 + m] + sx[n][2] * sB[256 + m];
        a *= TWO_PI;
        float s, c;
        sincosf(a, &s, &c);
        sF[n * FSTR + m] = c;
        sF[n * FSTR + 128 + m] = s;
    }
    __syncthreads();

    // GEMM: 64 nodes x 96 feats, K=256. 16x16 thread grid, 4 nodes x 6 feats each.
    const int tf = t & 15, tn = t >> 4;
    float acc[4][6];
#pragma unroll
    for (int i = 0; i < 4; i++)
#pragma unroll
        for (int j = 0; j < 6; j++) acc[i][j] = 0.f;

    const float* fbase = sF + (tn * 4) * FSTR;
    const float* wbase = sW + tf * 6;
#pragma unroll 4
    for (int k = 0; k < 256; k++) {
        float a0 = fbase[0 * FSTR + k];
        float a1 = fbase[1 * FSTR + k];
        float a2 = fbase[2 * FSTR + k];
        float a3 = fbase[3 * FSTR + k];
        float b[6];
#pragma unroll
        for (int j = 0; j < 6; j++) b[j] = wbase[k * 96 + j];
#pragma unroll
        for (int j = 0; j < 6; j++) {
            acc[0][j] = fmaf(a0, b[j], acc[0][j]);
            acc[1][j] = fmaf(a1, b[j], acc[1][j]);
            acc[2][j] = fmaf(a2, b[j], acc[2][j]);
            acc[3][j] = fmaf(a3, b[j], acc[3][j]);
        }
    }
#pragma unroll
    for (int i = 0; i < 4; i++) {
        int n = n0 + tn * 4 + i;
        if (n < nNodes) {
#pragma unroll
            for (int j = 0; j < 6; j++)
                g_xemb[n * 96 + tf * 6 + j] = acc[i][j] + bp[tf * 6 + j];
        }
    }
}

// ---------------- kernel 2: edge scatter (sum + degree) ----------------
// Edge index dtype is detected on-device: if stored as int64 (little-endian,
// values < 2^31), every odd 32-bit word is 0. For int32 random indices the
// probability of 4 odd words all being 0 is ~(1/50000)^4. Deterministic.
__global__ __launch_bounds__(256) void k_scatter(
    const void* __restrict__ ei, int E)
{
    int idx = blockIdx.x * blockDim.x + threadIdx.x;
    int total = E * 24;                 // 24 float4 chunks per edge (96 floats)
    if (idx >= total) return;
    int e = idx / 24, c = idx % 24;

    const int* e32 = (const int*)ei;
    bool is64 = (e32[1] == 0) & (e32[3] == 0) & (e32[5] == 0) & (e32[7] == 0);

    int s, d;
    if (is64) {
        const long long* e64 = (const long long*)ei;
        s = (int)e64[e];
        d = (int)e64[E + e];
    } else {
        s = e32[e];
        d = e32[E + e];
    }
    const float4 v = *(const float4*)(&g_xemb[s * 96 + c * 4]);
    float* a = &g_agg[d * 96 + c * 4];
    atomicAdd(a + 0, v.x);
    atomicAdd(a + 1, v.y);
    atomicAdd(a + 2, v.z);
    atomicAdd(a + 3, v.w);
    if (c == 0) atomicAdd(&g_deg[d], 1.0f);
}

// ---------------- kernel 3: fusion GEMM + BN stats ----------------
// combined[N,192] = [x_embed | agg/deg] @ W_fus[192,96] + b -> d_out; accumulate sum/sq
#define CSTR 198

__global__ __launch_bounds__(256) void k_fuse(
    const float* __restrict__ Wf, const float* __restrict__ bf,
    float* __restrict__ out, int nNodes)
{
    extern __shared__ float sm[];
    float* sW = sm;                 // 192*96
    float* sC = sm + 192 * 96;      // TN*CSTR
    __shared__ float sinv[TN];
    __shared__ float ssum[FF];
    __shared__ float ssq[FF];

    const int t = threadIdx.x;
    const int n0 = blockIdx.x * TN;

    for (int i = t; i < 192 * 96; i += 256) sW[i] = Wf[i];
    if (t < TN) {
        int n = n0 + t;
        float d = (n < nNodes) ? g_deg[n] : 1.f;
        sinv[t] = 1.0f / fmaxf(d, 1.0f);
    }
    if (t < FF) { ssum[t] = 0.f; ssq[t] = 0.f; }
    __syncthreads();

    for (int i = t; i < TN * 96; i += 256) {
        int n = i / 96, f = i % 96;
        int gn = n0 + n;
        float e = (gn < nNodes) ? g_xemb[gn * 96 + f] : 0.f;
        float a = (gn < nNodes) ? g_agg[gn * 96 + f] * sinv[n] : 0.f;
        sC[n * CSTR + f] = e;
        sC[n * CSTR + 96 + f] = a;
    }
    __syncthreads();

    const int tf = t & 15, tn = t >> 4;
    float acc[4][6];
#pragma unroll
    for (int i = 0; i < 4; i++)
#pragma unroll
        for (int j = 0; j < 6; j++) acc[i][j] = 0.f;

    const float* cbase = sC + (tn * 4) * CSTR;
    const float* wbase = sW + tf * 6;
#pragma unroll 4
    for (int k = 0; k < 192; k++) {
        float a0 = cbase[0 * CSTR + k];
        float a1 = cbase[1 * CSTR + k];
        float a2 = cbase[2 * CSTR + k];
        float a3 = cbase[3 * CSTR + k];
        float b[6];
#pragma unroll
        for (int j = 0; j < 6; j++) b[j] = wbase[k * 96 + j];
#pragma unroll
        for (int j = 0; j < 6; j++) {
            acc[0][j] = fmaf(a0, b[j], acc[0][j]);
            acc[1][j] = fmaf(a1, b[j], acc[1][j]);
            acc[2][j] = fmaf(a2, b[j], acc[2][j]);
            acc[3][j] = fmaf(a3, b[j], acc[3][j]);
        }
    }

    float psum[6], psq[6];
#pragma unroll
    for (int j = 0; j < 6; j++) { psum[j] = 0.f; psq[j] = 0.f; }

#pragma unroll
    for (int i = 0; i < 4; i++) {
        int n = n0 + tn * 4 + i;
        if (n < nNodes) {
#pragma unroll
            for (int j = 0; j < 6; j++) {
                float v = acc[i][j] + bf[tf * 6 + j];
                out[n * 96 + tf * 6 + j] = v;
                psum[j] += v;
                psq[j] += v * v;
            }
        }
    }
#pragma unroll
    for (int j = 0; j < 6; j++) {
        atomicAdd(&ssum[tf * 6 + j], psum[j]);
        atomicAdd(&ssq[tf * 6 + j], psq[j]);
    }
    __syncthreads();
    if (t < FF) {
        atomicAdd(&g_sum[t], ssum[t]);
        atomicAdd(&g_sq[t], ssq[t]);
    }
}

// ---------------- kernel 4: BatchNorm + exact GELU (in-place on d_out) ----
__global__ __launch_bounds__(256) void k_bn(
    float* __restrict__ out, const float* __restrict__ gamma,
    const float* __restrict__ beta, int nNodes)
{
    __shared__ float sscale[FF], sshift[FF];
    if (threadIdx.x < FF) {
        int f = threadIdx.x;
        float invN = 1.0f / (float)nNodes;
        float mean = g_sum[f] * invN;
        float var = g_sq[f] * invN - mean * mean;
        float rs = rsqrtf(var + 1e-5f);
        float sc = rs * gamma[f];
        sscale[f] = sc;
        sshift[f] = beta[f] - mean * sc;
    }
    __syncthreads();
    int total = nNodes * FF;
    int idx = blockIdx.x * blockDim.x + threadIdx.x;
    int stride = gridDim.x * blockDim.x;
    for (int i = idx; i < total; i += stride) {
        int f = i % FF;
        float y = out[i] * sscale[f] + sshift[f];
        out[i] = 0.5f * y * (1.0f + erff(y * 0.70710678118654752f));
    }
}

// ---------------- launch ----------------
extern "C" void kernel_launch(void* const* d_in, const int* in_sizes, int n_in,
                              void* d_out, int out_size)
{
    const float* x      = (const float*)d_in[0];
    const float* B      = (const float*)d_in[1];
    const float* Wp     = (const float*)d_in[2];
    const float* bp     = (const float*)d_in[3];
    const float* Wf     = (const float*)d_in[4];
    const float* bf     = (const float*)d_in[5];
    const float* gamma  = (const float*)d_in[6];
    const float* beta   = (const float*)d_in[7];
    const void* ei      = d_in[8];

    int nNodes = in_sizes[0] / 3;
    int E = in_sizes[8] / 2;

    const int smem_embed = (256 * 96 + TN * FSTR) * 4;
    const int smem_fuse  = (192 * 96 + TN * CSTR) * 4;
    cudaFuncSetAttribute(k_embed, cudaFuncAttributeMaxDynamicSharedMemorySize, smem_embed);
    cudaFuncSetAttribute(k_fuse,  cudaFuncAttributeMaxDynamicSharedMemorySize, smem_fuse);

    int nTiles = (nNodes + TN - 1) / TN;

    // zero scratch
    k_zero<<<4096, 256>>>(nNodes * FF, nNodes);
    // embed
    k_embed<<<nTiles, 256, smem_embed>>>(x, B, Wp, bp, nNodes);
    // scatter
    {
        int total = E * 24;
        int blocks = (total + 255) / 256;
        k_scatter<<<blocks, 256>>>(ei, E);
    }
    // fuse + stats
    k_fuse<<<nTiles, 256, smem_fuse>>>(Wf, bf, (float*)d_out, nNodes);
    // bn + gelu
    {
        int total = nNodes * FF;
        int blocks = (total + 1023) / 1024;
        k_bn<<<blocks, 256>>>((float*)d_out, gamma, beta, nNodes);
    }
}

// round 4
// speedup vs baseline: 1.7334x; 1.7334x over previous
#include <cuda_runtime.h>
#include <cuda_bf16.h>
#include <math.h>

#define NN 50000
#define FF 96

// ---------------- scratch (device globals; no allocation allowed) ----------
__device__ float g_xemb[NN * FF];   // x_embed
__device__ float g_agg[NN * FF];    // scatter sum
__device__ float g_deg[NN];         // degree
__device__ float g_sum[FF];         // BN sum
__device__ float g_sq[FF];          // BN sum of squares

// ---------------- kernel 0: zero scratch ----------------
__global__ void k_zero(int nAgg, int nDeg) {
    int idx = blockIdx.x * blockDim.x + threadIdx.x;
    int stride = gridDim.x * blockDim.x;
    for (int i = idx; i < nAgg; i += stride) g_agg[i] = 0.f;
    for (int i = idx; i < nDeg; i += stride) g_deg[i] = 0.f;
    if (idx < FF) { g_sum[idx] = 0.f; g_sq[idx] = 0.f; }
}

// ---------------- kernel 1: Fourier embed + projection (K-chunked) --------
// K order is permuted to (cos_0,sin_0,cos_1,sin_1,...): chunk c covers
// m in [32c, 32c+32); each chunk's sincos is computed on the fly and the
// matching W rows (m for even kc, 128+m for odd kc) are staged per chunk.
#define ETN 64     // nodes per block
#define EKC 64     // K per chunk (32 m values); 4 chunks cover K=256
#define ESTR 68    // A-chunk smem stride

__global__ __launch_bounds__(256) void k_embed(
    const float* __restrict__ x, const float* __restrict__ B,
    const float* __restrict__ Wp, const float* __restrict__ bp, int nNodes)
{
    __shared__ float sW[EKC * 96];       // 24.6 KB
    __shared__ float sF[ETN * ESTR];     // 17.4 KB
    __shared__ float sx[ETN][3];
    __shared__ float sB[3 * 128];

    const int t = threadIdx.x;
    const int n0 = blockIdx.x * ETN;

    for (int i = t; i < 3 * 128; i += 256) sB[i] = B[i];
    for (int i = t; i < ETN * 3; i += 256) {
        int n = n0 + i / 3;
        sx[i / 3][i % 3] = (n < nNodes) ? x[n * 3 + (i % 3)] : 0.f;
    }

    const int tf = t & 15, tn = t >> 4;
    float acc[4][6];
#pragma unroll
    for (int i = 0; i < 4; i++)
#pragma unroll
        for (int j = 0; j < 6; j++) acc[i][j] = 0.f;

    const float TWO_PI = 6.283185307179586f;

    for (int c = 0; c < 4; c++) {
        __syncthreads();   // protect previous chunk's consumers
        // stage W chunk (row-permuted)
        for (int i = t; i < EKC * 96; i += 256) {
            int kc = i / 96, f = i - kc * 96;
            int m = c * 32 + (kc >> 1);
            int row = (kc & 1) ? (128 + m) : m;
            sW[i] = Wp[row * 96 + f];
        }
        // compute ffm chunk: 64 nodes x 32 m
        for (int i = t; i < ETN * 32; i += 256) {
            int n = i >> 5, j = i & 31;
            int m = c * 32 + j;
            float a = sx[n][0] * sB[m] + sx[n][1] * sB[128 + m] + sx[n][2] * sB[256 + m];
            a *= TWO_PI;
            float s, cv;
            sincosf(a, &s, &cv);
            sF[n * ESTR + 2 * j] = cv;
            sF[n * ESTR + 2 * j + 1] = s;
        }
        __syncthreads();

        const float* fbase = sF + (tn * 4) * ESTR;
        const float* wbase = sW + tf * 6;
#pragma unroll 4
        for (int k = 0; k < EKC; k++) {
            float a0 = fbase[0 * ESTR + k];
            float a1 = fbase[1 * ESTR + k];
            float a2 = fbase[2 * ESTR + k];
            float a3 = fbase[3 * ESTR + k];
            float b[6];
#pragma unroll
            for (int j = 0; j < 6; j++) b[j] = wbase[k * 96 + j];
#pragma unroll
            for (int j = 0; j < 6; j++) {
                acc[0][j] = fmaf(a0, b[j], acc[0][j]);
                acc[1][j] = fmaf(a1, b[j], acc[1][j]);
                acc[2][j] = fmaf(a2, b[j], acc[2][j]);
                acc[3][j] = fmaf(a3, b[j], acc[3][j]);
            }
        }
    }

#pragma unroll
    for (int i = 0; i < 4; i++) {
        int n = n0 + tn * 4 + i;
        if (n < nNodes) {
#pragma unroll
            for (int j = 0; j < 6; j++)
                g_xemb[n * 96 + tf * 6 + j] = acc[i][j] + bp[tf * 6 + j];
        }
    }
}

// ---------------- kernel 2: edge scatter (sum + degree) ----------------
__global__ __launch_bounds__(256) void k_scatter(
    const void* __restrict__ ei, int E)
{
    int idx = blockIdx.x * blockDim.x + threadIdx.x;
    int total = E * 24;                 // 24 float4 chunks per edge
    if (idx >= total) return;
    int e = idx / 24, c = idx % 24;

    const int* e32 = (const int*)ei;
    bool is64 = (e32[1] == 0) & (e32[3] == 0) & (e32[5] == 0) & (e32[7] == 0);

    int s, d;
    if (is64) {
        const long long* e64 = (const long long*)ei;
        s = (int)e64[e];
        d = (int)e64[E + e];
    } else {
        s = e32[e];
        d = e32[E + e];
    }
    const float4 v = *(const float4*)(&g_xemb[s * 96 + c * 4]);
    float* a = &g_agg[d * 96 + c * 4];
#if __CUDA_ARCH__ >= 900
    asm volatile("red.global.add.v4.f32 [%0], {%1, %2, %3, %4};"
                 :: "l"(a), "f"(v.x), "f"(v.y), "f"(v.z), "f"(v.w) : "memory");
#else
    atomicAdd(a + 0, v.x);
    atomicAdd(a + 1, v.y);
    atomicAdd(a + 2, v.z);
    atomicAdd(a + 3, v.w);
#endif
    if (c == 0) atomicAdd(&g_deg[d], 1.0f);
}

// ---------------- kernel 3: fusion GEMM + BN stats (K-chunked, dyn smem) --
// combined[N,192] = [x_embed | agg/deg] @ W_fus + b; chunk0 = embed half,
// chunk1 = agg half. Big tiles live in dynamic smem (62.5 KB > 48 KB static cap).
#define FKC 96     // K per chunk; 2 chunks cover K=192
#define CSTR 100   // A-chunk smem stride

__global__ __launch_bounds__(256) void k_fuse(
    const float* __restrict__ Wf, const float* __restrict__ bf,
    float* __restrict__ out, int nNodes)
{
    extern __shared__ float sm[];
    float* sW = sm;                  // FKC*96  = 9216 floats
    float* sC = sm + FKC * 96;       // ETN*CSTR = 6400 floats
    __shared__ float sinv[ETN];
    __shared__ float ssum[FF];
    __shared__ float ssq[FF];

    const int t = threadIdx.x;
    const int n0 = blockIdx.x * ETN;

    if (t < ETN) {
        int n = n0 + t;
        float d = (n < nNodes) ? g_deg[n] : 1.f;
        sinv[t] = 1.0f / fmaxf(d, 1.0f);
    }
    if (t < FF) { ssum[t] = 0.f; ssq[t] = 0.f; }

    const int tf = t & 15, tn = t >> 4;
    float acc[4][6];
#pragma unroll
    for (int i = 0; i < 4; i++)
#pragma unroll
        for (int j = 0; j < 6; j++) acc[i][j] = 0.f;

    for (int c = 0; c < 2; c++) {
        __syncthreads();
        for (int i = t; i < FKC * 96; i += 256)
            sW[i] = Wf[c * FKC * 96 + i];
        for (int i = t; i < ETN * 96; i += 256) {
            int n = i / 96, f = i - n * 96;
            int gn = n0 + n;
            float v;
            if (c == 0)
                v = (gn < nNodes) ? g_xemb[gn * 96 + f] : 0.f;
            else
                v = (gn < nNodes) ? g_agg[gn * 96 + f] * sinv[n] : 0.f;
            sC[n * CSTR + f] = v;
        }
        __syncthreads();

        const float* cbase = sC + (tn * 4) * CSTR;
        const float* wbase = sW + tf * 6;
#pragma unroll 4
        for (int k = 0; k < FKC; k++) {
            float a0 = cbase[0 * CSTR + k];
            float a1 = cbase[1 * CSTR + k];
            float a2 = cbase[2 * CSTR + k];
            float a3 = cbase[3 * CSTR + k];
            float b[6];
#pragma unroll
            for (int j = 0; j < 6; j++) b[j] = wbase[k * 96 + j];
#pragma unroll
            for (int j = 0; j < 6; j++) {
                acc[0][j] = fmaf(a0, b[j], acc[0][j]);
                acc[1][j] = fmaf(a1, b[j], acc[1][j]);
                acc[2][j] = fmaf(a2, b[j], acc[2][j]);
                acc[3][j] = fmaf(a3, b[j], acc[3][j]);
            }
        }
    }

    float psum[6], psq[6];
#pragma unroll
    for (int j = 0; j < 6; j++) { psum[j] = 0.f; psq[j] = 0.f; }

#pragma unroll
    for (int i = 0; i < 4; i++) {
        int n = n0 + tn * 4 + i;
        if (n < nNodes) {
#pragma unroll
            for (int j = 0; j < 6; j++) {
                float v = acc[i][j] + bf[tf * 6 + j];
                out[n * 96 + tf * 6 + j] = v;
                psum[j] += v;
                psq[j] += v * v;
            }
        }
    }
#pragma unroll
    for (int j = 0; j < 6; j++) {
        atomicAdd(&ssum[tf * 6 + j], psum[j]);
        atomicAdd(&ssq[tf * 6 + j], psq[j]);
    }
    __syncthreads();
    if (t < FF) {
        atomicAdd(&g_sum[t], ssum[t]);
        atomicAdd(&g_sq[t], ssq[t]);
    }
}

// ---------------- kernel 4: BatchNorm + exact GELU (in-place, float4) -----
__global__ __launch_bounds__(256) void k_bn(
    float* __restrict__ out, const float* __restrict__ gamma,
    const float* __restrict__ beta, int nNodes)
{
    __shared__ float sscale[FF], sshift[FF];
    if (threadIdx.x < FF) {
        int f = threadIdx.x;
        float invN = 1.0f / (float)nNodes;
        float mean = g_sum[f] * invN;
        float var = g_sq[f] * invN - mean * mean;
        float rs = rsqrtf(var + 1e-5f);
        float sc = rs * gamma[f];
        sscale[f] = sc;
        sshift[f] = beta[f] - mean * sc;
    }
    __syncthreads();
    int total4 = nNodes * (FF / 4);
    int idx = blockIdx.x * blockDim.x + threadIdx.x;
    int stride = gridDim.x * blockDim.x;
    for (int i = idx; i < total4; i += stride) {
        int f4 = (i % 24) * 4;
        float4 v = ((float4*)out)[i];
        float r[4] = {v.x, v.y, v.z, v.w};
#pragma unroll
        for (int j = 0; j < 4; j++) {
            float y = r[j] * sscale[f4 + j] + sshift[f4 + j];
            r[j] = 0.5f * y * (1.0f + erff(y * 0.70710678118654752f));
        }
        ((float4*)out)[i] = make_float4(r[0], r[1], r[2], r[3]);
    }
}

// ---------------- launch ----------------
extern "C" void kernel_launch(void* const* d_in, const int* in_sizes, int n_in,
                              void* d_out, int out_size)
{
    const float* x      = (const float*)d_in[0];
    const float* B      = (const float*)d_in[1];
    const float* Wp     = (const float*)d_in[2];
    const float* bp     = (const float*)d_in[3];
    const float* Wf     = (const float*)d_in[4];
    const float* bf     = (const float*)d_in[5];
    const float* gamma  = (const float*)d_in[6];
    const float* beta   = (const float*)d_in[7];
    const void* ei      = d_in[8];

    int nNodes = in_sizes[0] / 3;
    int E = in_sizes[8] / 2;
    int nTiles = (nNodes + ETN - 1) / ETN;

    const int smem_fuse = (FKC * 96 + ETN * CSTR) * 4;   // 62.5 KB
    cudaFuncSetAttribute(k_fuse, cudaFuncAttributeMaxDynamicSharedMemorySize, smem_fuse);

    k_zero<<<4096, 256>>>(nNodes * FF, nNodes);
    k_embed<<<nTiles, 256>>>(x, B, Wp, bp, nNodes);
    {
        int total = E * 24;
        k_scatter<<<(total + 255) / 256, 256>>>(ei, E);
    }
    k_fuse<<<nTiles, 256, smem_fuse>>>(Wf, bf, (float*)d_out, nNodes);
    {
        int total4 = nNodes * (FF / 4);
        k_bn<<<(total4 + 1023) / 1024, 256>>>((float*)d_out, gamma, beta, nNodes);
    }
}

// round 5
// speedup vs baseline: 1.7475x; 1.0081x over previous
#include <cuda_runtime.h>
#include <cuda_bf16.h>
#include <math.h>

#define NN 50000
#define FF 96

// ---------------- scratch (device globals; no allocation allowed) ----------
__device__ float g_xemb[NN * FF];   // x_embed
__device__ float g_agg[NN * FF];    // scatter sum
__device__ float g_deg[NN];         // degree
__device__ float g_sum[FF];         // BN sum
__device__ float g_sq[FF];          // BN sum of squares

// ---------------- kernel 0: zero scratch ----------------
__global__ void k_zero(int nAgg, int nDeg) {
    int idx = blockIdx.x * blockDim.x + threadIdx.x;
    int stride = gridDim.x * blockDim.x;
    for (int i = idx; i < nAgg; i += stride) g_agg[i] = 0.f;
    for (int i = idx; i < nDeg; i += stride) g_deg[i] = 0.f;
    if (idx < FF) { g_sum[idx] = 0.f; g_sq[idx] = 0.f; }
}

// ---------------- kernel 1: Fourier embed + projection (K-chunked) --------
#define ETN 64     // nodes per block
#define EKC 64     // K per chunk (32 m values); 4 chunks cover K=256
#define ESTR 68    // A-chunk smem stride (272 B, 16B-aligned)

__global__ __launch_bounds__(256) void k_embed(
    const float* __restrict__ x, const float* __restrict__ B,
    const float* __restrict__ Wp, const float* __restrict__ bp, int nNodes)
{
    __shared__ float sW[EKC * 96];       // 24.6 KB
    __shared__ float sF[ETN * ESTR];     // 17.4 KB
    __shared__ float sx[ETN][3];
    __shared__ float sB[3 * 128];

    const int t = threadIdx.x;
    const int n0 = blockIdx.x * ETN;

    for (int i = t; i < 3 * 128; i += 256) sB[i] = B[i];
    for (int i = t; i < ETN * 3; i += 256) {
        int n = n0 + i / 3;
        sx[i / 3][i % 3] = (n < nNodes) ? x[n * 3 + (i % 3)] : 0.f;
    }

    const int tf = t & 15, tn = t >> 4;
    float acc[4][6];
#pragma unroll
    for (int i = 0; i < 4; i++)
#pragma unroll
        for (int j = 0; j < 6; j++) acc[i][j] = 0.f;

    const float TWO_PI = 6.283185307179586f;

    for (int c = 0; c < 4; c++) {
        __syncthreads();   // protect previous chunk's consumers
        // stage W chunk (row-permuted: k = 2m_local + (sin?1:0))
        for (int i = t; i < EKC * 96; i += 256) {
            int kc = i / 96, f = i - kc * 96;
            int m = c * 32 + (kc >> 1);
            int row = (kc & 1) ? (128 + m) : m;
            sW[i] = Wp[row * 96 + f];
        }
        // compute ffm chunk: 64 nodes x 32 m
        for (int i = t; i < ETN * 32; i += 256) {
            int n = i >> 5, j = i & 31;
            int m = c * 32 + j;
            float a = sx[n][0] * sB[m] + sx[n][1] * sB[128 + m] + sx[n][2] * sB[256 + m];
            a *= TWO_PI;
            float s, cv;
            sincosf(a, &s, &cv);
            sF[n * ESTR + 2 * j] = cv;
            sF[n * ESTR + 2 * j + 1] = s;
        }
        __syncthreads();

        const float* fbase = sF + (tn * 4) * ESTR;
        const float* wbase = sW + tf * 6;
        for (int k4 = 0; k4 < EKC / 4; k4++) {
            float4 a0 = *(const float4*)(fbase + 0 * ESTR + k4 * 4);
            float4 a1 = *(const float4*)(fbase + 1 * ESTR + k4 * 4);
            float4 a2 = *(const float4*)(fbase + 2 * ESTR + k4 * 4);
            float4 a3 = *(const float4*)(fbase + 3 * ESTR + k4 * 4);
            const float* ap0 = (const float*)&a0;
            const float* ap1 = (const float*)&a1;
            const float* ap2 = (const float*)&a2;
            const float* ap3 = (const float*)&a3;
#pragma unroll
            for (int kk = 0; kk < 4; kk++) {
                const float2* wb = (const float2*)(wbase + (k4 * 4 + kk) * 96);
                float2 b0 = wb[0], b1 = wb[1], b2 = wb[2];
                float b[6] = {b0.x, b0.y, b1.x, b1.y, b2.x, b2.y};
                float v0 = ap0[kk], v1 = ap1[kk], v2 = ap2[kk], v3 = ap3[kk];
#pragma unroll
                for (int j = 0; j < 6; j++) {
                    acc[0][j] = fmaf(v0, b[j], acc[0][j]);
                    acc[1][j] = fmaf(v1, b[j], acc[1][j]);
                    acc[2][j] = fmaf(v2, b[j], acc[2][j]);
                    acc[3][j] = fmaf(v3, b[j], acc[3][j]);
                }
            }
        }
    }

#pragma unroll
    for (int i = 0; i < 4; i++) {
        int n = n0 + tn * 4 + i;
        if (n < nNodes) {
#pragma unroll
            for (int j = 0; j < 6; j++)
                g_xemb[n * 96 + tf * 6 + j] = acc[i][j] + bp[tf * 6 + j];
        }
    }
}

// ---------------- kernel 2: edge scatter (sum + degree) ----------------
__global__ __launch_bounds__(256) void k_scatter(
    const void* __restrict__ ei, int E)
{
    int idx = blockIdx.x * blockDim.x + threadIdx.x;
    int total = E * 24;                 // 24 float4 chunks per edge
    if (idx >= total) return;
    int e = idx / 24, c = idx % 24;

    const int* e32 = (const int*)ei;
    bool is64 = (e32[1] == 0) & (e32[3] == 0) & (e32[5] == 0) & (e32[7] == 0);

    int s, d;
    if (is64) {
        const long long* e64 = (const long long*)ei;
        s = (int)e64[e];
        d = (int)e64[E + e];
    } else {
        s = e32[e];
        d = e32[E + e];
    }
    const float4 v = *(const float4*)(&g_xemb[s * 96 + c * 4]);
    float* a = &g_agg[d * 96 + c * 4];
#if __CUDA_ARCH__ >= 900
    asm volatile("red.global.add.v4.f32 [%0], {%1, %2, %3, %4};"
                 :: "l"(a), "f"(v.x), "f"(v.y), "f"(v.z), "f"(v.w) : "memory");
#else
    atomicAdd(a + 0, v.x);
    atomicAdd(a + 1, v.y);
    atomicAdd(a + 2, v.z);
    atomicAdd(a + 3, v.w);
#endif
    if (c == 0) atomicAdd(&g_deg[d], 1.0f);
}

// ---------------- kernel 3: fusion GEMM + BN stats (K-chunked, dyn smem) --
#define FKC 96     // K per chunk; 2 chunks cover K=192
#define CSTR 100   // A-chunk smem stride (400 B, 16B-aligned)

__global__ __launch_bounds__(256) void k_fuse(
    const float* __restrict__ Wf, const float* __restrict__ bf,
    float* __restrict__ out, int nNodes)
{
    extern __shared__ float sm[];
    float* sW = sm;                  // FKC*96  = 9216 floats
    float* sC = sm + FKC * 96;       // ETN*CSTR = 6400 floats (base 36864B, aligned)
    __shared__ float sinv[ETN];
    __shared__ float ssum[FF];
    __shared__ float ssq[FF];

    const int t = threadIdx.x;
    const int n0 = blockIdx.x * ETN;

    if (t < ETN) {
        int n = n0 + t;
        float d = (n < nNodes) ? g_deg[n] : 1.f;
        sinv[t] = 1.0f / fmaxf(d, 1.0f);
    }
    if (t < FF) { ssum[t] = 0.f; ssq[t] = 0.f; }

    const int tf = t & 15, tn = t >> 4;
    float acc[4][6];
#pragma unroll
    for (int i = 0; i < 4; i++)
#pragma unroll
        for (int j = 0; j < 6; j++) acc[i][j] = 0.f;

    for (int c = 0; c < 2; c++) {
        __syncthreads();
        for (int i = t; i < FKC * 96; i += 256)
            sW[i] = Wf[c * FKC * 96 + i];
        for (int i = t; i < ETN * 96; i += 256) {
            int n = i / 96, f = i - n * 96;
            int gn = n0 + n;
            float v;
            if (c == 0)
                v = (gn < nNodes) ? g_xemb[gn * 96 + f] : 0.f;
            else
                v = (gn < nNodes) ? g_agg[gn * 96 + f] * sinv[n] : 0.f;
            sC[n * CSTR + f] = v;
        }
        __syncthreads();

        const float* cbase = sC + (tn * 4) * CSTR;
        const float* wbase = sW + tf * 6;
        for (int k4 = 0; k4 < FKC / 4; k4++) {
            float4 a0 = *(const float4*)(cbase + 0 * CSTR + k4 * 4);
            float4 a1 = *(const float4*)(cbase + 1 * CSTR + k4 * 4);
            float4 a2 = *(const float4*)(cbase + 2 * CSTR + k4 * 4);
            float4 a3 = *(const float4*)(cbase + 3 * CSTR + k4 * 4);
            const float* ap0 = (const float*)&a0;
            const float* ap1 = (const float*)&a1;
            const float* ap2 = (const float*)&a2;
            const float* ap3 = (const float*)&a3;
#pragma unroll
            for (int kk = 0; kk < 4; kk++) {
                const float2* wb = (const float2*)(wbase + (k4 * 4 + kk) * 96);
                float2 b0 = wb[0], b1 = wb[1], b2 = wb[2];
                float b[6] = {b0.x, b0.y, b1.x, b1.y, b2.x, b2.y};
                float v0 = ap0[kk], v1 = ap1[kk], v2 = ap2[kk], v3 = ap3[kk];
#pragma unroll
                for (int j = 0; j < 6; j++) {
                    acc[0][j] = fmaf(v0, b[j], acc[0][j]);
                    acc[1][j] = fmaf(v1, b[j], acc[1][j]);
                    acc[2][j] = fmaf(v2, b[j], acc[2][j]);
                    acc[3][j] = fmaf(v3, b[j], acc[3][j]);
                }
            }
        }
    }

    float psum[6], psq[6];
#pragma unroll
    for (int j = 0; j < 6; j++) { psum[j] = 0.f; psq[j] = 0.f; }

#pragma unroll
    for (int i = 0; i < 4; i++) {
        int n = n0 + tn * 4 + i;
        if (n < nNodes) {
#pragma unroll
            for (int j = 0; j < 6; j++) {
                float v = acc[i][j] + bf[tf * 6 + j];
                out[n * 96 + tf * 6 + j] = v;
                psum[j] += v;
                psq[j] += v * v;
            }
        }
    }
#pragma unroll
    for (int j = 0; j < 6; j++) {
        atomicAdd(&ssum[tf * 6 + j], psum[j]);
        atomicAdd(&ssq[tf * 6 + j], psq[j]);
    }
    __syncthreads();
    if (t < FF) {
        atomicAdd(&g_sum[t], ssum[t]);
        atomicAdd(&g_sq[t], ssq[t]);
    }
}

// ---------------- kernel 4: BatchNorm + exact GELU (in-place, float4) -----
__global__ __launch_bounds__(256) void k_bn(
    float* __restrict__ out, const float* __restrict__ gamma,
    const float* __restrict__ beta, int nNodes)
{
    __shared__ float sscale[FF], sshift[FF];
    if (threadIdx.x < FF) {
        int f = threadIdx.x;
        float invN = 1.0f / (float)nNodes;
        float mean = g_sum[f] * invN;
        float var = g_sq[f] * invN - mean * mean;
        float rs = rsqrtf(var + 1e-5f);
        float sc = rs * gamma[f];
        sscale[f] = sc;
        sshift[f] = beta[f] - mean * sc;
    }
    __syncthreads();
    int total4 = nNodes * (FF / 4);
    int idx = blockIdx.x * blockDim.x + threadIdx.x;
    int stride = gridDim.x * blockDim.x;
    for (int i = idx; i < total4; i += stride) {
        int f4 = (i % 24) * 4;
        float4 v = ((float4*)out)[i];
        float r[4] = {v.x, v.y, v.z, v.w};
#pragma unroll
        for (int j = 0; j < 4; j++) {
            float y = r[j] * sscale[f4 + j] + sshift[f4 + j];
            r[j] = 0.5f * y * (1.0f + erff(y * 0.70710678118654752f));
        }
        ((float4*)out)[i] = make_float4(r[0], r[1], r[2], r[3]);
    }
}

// ---------------- launch ----------------
extern "C" void kernel_launch(void* const* d_in, const int* in_sizes, int n_in,
                              void* d_out, int out_size)
{
    const float* x      = (const float*)d_in[0];
    const float* B      = (const float*)d_in[1];
    const float* Wp     = (const float*)d_in[2];
    const float* bp     = (const float*)d_in[3];
    const float* Wf     = (const float*)d_in[4];
    const float* bf     = (const float*)d_in[5];
    const float* gamma  = (const float*)d_in[6];
    const float* beta   = (const float*)d_in[7];
    const void* ei      = d_in[8];

    int nNodes = in_sizes[0] / 3;
    int E = in_sizes[8] / 2;
    int nTiles = (nNodes + ETN - 1) / ETN;

    const int smem_fuse = (FKC * 96 + ETN * CSTR) * 4;   // 62.5 KB
    cudaFuncSetAttribute(k_fuse, cudaFuncAttributeMaxDynamicSharedMemorySize, smem_fuse);

    k_zero<<<4096, 256>>>(nNodes * FF, nNodes);
    k_embed<<<nTiles, 256>>>(x, B, Wp, bp, nNodes);
    {
        int total = E * 24;
        k_scatter<<<(total + 255) / 256, 256>>>(ei, E);
    }
    k_fuse<<<nTiles, 256, smem_fuse>>>(Wf, bf, (float*)d_out, nNodes);
    {
        int total4 = nNodes * (FF / 4);
        k_bn<<<(total4 + 1023) / 1024, 256>>>((float*)d_out, gamma, beta, nNodes);
    }
}

// round 9
// speedup vs baseline: 1.8179x; 1.0403x over previous
#include <cuda_runtime.h>
#include <cuda_bf16.h>
#include <math.h>
#include <stdint.h>

#define NN 50000
#define FF 96
#define EM 128   // nodes per GEMM CTA (tile M)

// ---------------- scratch (device globals; no allocation allowed) ----------
__device__ float g_xemb[NN * FF];
__device__ float g_agg[NN * FF];
__device__ float g_deg[NN];
__device__ float g_sum[FF];
__device__ float g_sq[FF];

// ---------------- helpers -------------------------------------------------
__device__ __forceinline__ uint32_t pack_bf16(float a, float b) {
    __nv_bfloat162 h = __floats2bfloat162_rn(a, b);   // .x=a (low 16), .y=b
    return *(uint32_t*)&h;
}
__device__ __forceinline__ void split2(float a, float b, uint32_t& hi, uint32_t& lo) {
    __nv_bfloat16 ha = __float2bfloat16(a);
    __nv_bfloat16 hb = __float2bfloat16(b);
    float la = a - __bfloat162float(ha);
    float lb = b - __bfloat162float(hb);
    __nv_bfloat162 hh; hh.x = ha; hh.y = hb;
    hi = *(uint32_t*)&hh;
    lo = pack_bf16(la, lb);
}
__device__ __forceinline__ void mma_bf16(float* d, const uint32_t* a, const uint32_t* b) {
    asm volatile(
        "mma.sync.aligned.m16n8k16.row.col.f32.bf16.bf16.f32 "
        "{%0,%1,%2,%3}, {%4,%5,%6,%7}, {%8,%9}, {%0,%1,%2,%3};"
        : "+f"(d[0]), "+f"(d[1]), "+f"(d[2]), "+f"(d[3])
        : "r"(a[0]), "r"(a[1]), "r"(a[2]), "r"(a[3]), "r"(b[0]), "r"(b[1]));
}

// ---------------- kernel 0: zero scratch ----------------
__global__ void k_zero(int nAgg, int nDeg) {
    int idx = blockIdx.x * blockDim.x + threadIdx.x;
    int stride = gridDim.x * blockDim.x;
    for (int i = idx; i < nAgg; i += stride) g_agg[i] = 0.f;
    for (int i = idx; i < nDeg; i += stride) g_deg[i] = 0.f;
    if (idx < FF) { g_sum[idx] = 0.f; g_sq[idx] = 0.f; }
}

// ================== kernel 1: Fourier embed + projection (HMMA) ===========
// D[128,96] = ffm[128,256] @ Wp'[96,256]^T, K order k=2m+(0:cos,1:sin).
// A in 2 K-chunks of 128; B staged fully. 3-term bf16 split.
#define ASTR_E 136   // A chunk stride (128+8) elem; frag bank inc 4
#define BSTR_E 280   // B stride (256+24) elem; frag bank inc 12

__global__ __launch_bounds__(256) void k_embed(
    const float* __restrict__ x, const float* __restrict__ B,
    const float* __restrict__ Wp, const float* __restrict__ bp, int nNodes)
{
    extern __shared__ char dyn[];
    __nv_bfloat16* sBhi = (__nv_bfloat16*)dyn;                    // 96*280
    __nv_bfloat16* sBlo = sBhi + 96 * BSTR_E;
    __nv_bfloat16* sAhi = sBlo + 96 * BSTR_E;                     // 128*136
    __nv_bfloat16* sAlo = sAhi + EM * ASTR_E;
    __shared__ float sx[EM][3];
    __shared__ float sb[384];

    const int t = threadIdx.x;
    const int lane = t & 31, wid = t >> 5;
    const int wm = wid & 3, wn = wid >> 2;       // warp grid 4(M) x 2(N)
    const int gp = lane >> 2, tg = lane & 3;     // groupID, threadID-in-group
    const int n0 = blockIdx.x * EM;

    for (int i = t; i < 384; i += 256) sb[i] = B[i];
    for (int i = t; i < EM * 3; i += 256) {
        int n = n0 + i / 3;
        sx[i / 3][i % 3] = (n < nNodes) ? x[n * 3 + (i % 3)] : 0.f;
    }
    // stage B: pair (cos,sin) per (n, m): cols (2m, 2m+1)
    for (int i = t; i < 96 * 128; i += 256) {
        int n = i % 96, m = i / 96;
        float w0 = Wp[m * 96 + n];
        float w1 = Wp[(128 + m) * 96 + n];
        uint32_t hi, lo;
        split2(w0, w1, hi, lo);
        *(uint32_t*)(sBhi + n * BSTR_E + 2 * m) = hi;
        *(uint32_t*)(sBlo + n * BSTR_E + 2 * m) = lo;
    }

    float acc[2][6][4];
#pragma unroll
    for (int i = 0; i < 2; i++)
#pragma unroll
        for (int j = 0; j < 6; j++)
#pragma unroll
            for (int q = 0; q < 4; q++) acc[i][j][q] = 0.f;

    const float TWO_PI = 6.283185307179586f;

    for (int c = 0; c < 2; c++) {
        __syncthreads();   // B/prev-chunk consumers done
        // stage A chunk: 128 nodes x 64 m -> local cols (2j, 2j+1)
        for (int i = t; i < EM * 64; i += 256) {
            int n = i >> 6, j = i & 63;
            int m = c * 64 + j;
            float a = sx[n][0] * sb[m] + sx[n][1] * sb[128 + m] + sx[n][2] * sb[256 + m];
            a *= TWO_PI;
            float sv, cv;
            sincosf(a, &sv, &cv);
            uint32_t hi, lo;
            split2(cv, sv, hi, lo);
            *(uint32_t*)(sAhi + n * ASTR_E + 2 * j) = hi;
            *(uint32_t*)(sAlo + n * ASTR_E + 2 * j) = lo;
        }
        __syncthreads();

#pragma unroll
        for (int s8 = 0; s8 < 8; s8++) {
            int kl = s8 * 16;            // A local k
            int kg = c * 128 + kl;       // B global k
            uint32_t ah[2][4], al[2][4], bh[6][2], bl[6][2];
#pragma unroll
            for (int ma = 0; ma < 2; ma++) {
                int r = wm * 32 + ma * 16 + gp;
                const __nv_bfloat16* p0 = sAhi + r * ASTR_E + kl + tg * 2;
                const __nv_bfloat16* p1 = sAlo + r * ASTR_E + kl + tg * 2;
                ah[ma][0] = *(uint32_t*)(p0);
                ah[ma][1] = *(uint32_t*)(p0 + 8 * ASTR_E);
                ah[ma][2] = *(uint32_t*)(p0 + 8);
                ah[ma][3] = *(uint32_t*)(p0 + 8 * ASTR_E + 8);
                al[ma][0] = *(uint32_t*)(p1);
                al[ma][1] = *(uint32_t*)(p1 + 8 * ASTR_E);
                al[ma][2] = *(uint32_t*)(p1 + 8);
                al[ma][3] = *(uint32_t*)(p1 + 8 * ASTR_E + 8);
            }
#pragma unroll
            for (int nb = 0; nb < 6; nb++) {
                int n = wn * 48 + nb * 8 + gp;
                const __nv_bfloat16* q0 = sBhi + n * BSTR_E + kg + tg * 2;
                const __nv_bfloat16* q1 = sBlo + n * BSTR_E + kg + tg * 2;
                bh[nb][0] = *(uint32_t*)(q0);
                bh[nb][1] = *(uint32_t*)(q0 + 8);
                bl[nb][0] = *(uint32_t*)(q1);
                bl[nb][1] = *(uint32_t*)(q1 + 8);
            }
#pragma unroll
            for (int ma = 0; ma < 2; ma++)
#pragma unroll
                for (int nb = 0; nb < 6; nb++) {
                    mma_bf16(acc[ma][nb], ah[ma], bh[nb]);
                    mma_bf16(acc[ma][nb], al[ma], bh[nb]);
                    mma_bf16(acc[ma][nb], ah[ma], bl[nb]);
                }
        }
    }

    // epilogue: rows wm*32+ma*16+gp (+8), cols wn*48+nb*8+tg*2
#pragma unroll
    for (int ma = 0; ma < 2; ma++) {
        int r0 = n0 + wm * 32 + ma * 16 + gp;
#pragma unroll
        for (int half = 0; half < 2; half++) {
            int r = r0 + half * 8;
            if (r < nNodes) {
#pragma unroll
                for (int nb = 0; nb < 6; nb++) {
                    int col = wn * 48 + nb * 8 + tg * 2;
                    float2 v;
                    v.x = acc[ma][nb][half * 2 + 0] + bp[col];
                    v.y = acc[ma][nb][half * 2 + 1] + bp[col + 1];
                    *(float2*)(&g_xemb[r * 96 + col]) = v;
                }
            }
        }
    }
}

// ---------------- kernel 2: edge scatter (sum + degree) ----------------
__global__ __launch_bounds__(256) void k_scatter(const void* __restrict__ ei, int E)
{
    int idx = blockIdx.x * blockDim.x + threadIdx.x;
    int total = E * 24;
    if (idx >= total) return;
    int e = idx / 24, c = idx % 24;

    const int* e32 = (const int*)ei;
    bool is64 = (e32[1] == 0) & (e32[3] == 0) & (e32[5] == 0) & (e32[7] == 0);

    int s, d;
    if (is64) {
        const long long* e64 = (const long long*)ei;
        s = (int)e64[e];
        d = (int)e64[E + e];
    } else {
        s = e32[e];
        d = e32[E + e];
    }
    const float4 v = *(const float4*)(&g_xemb[s * 96 + c * 4]);
    float* a = &g_agg[d * 96 + c * 4];
#if __CUDA_ARCH__ >= 900
    asm volatile("red.global.add.v4.f32 [%0], {%1, %2, %3, %4};"
                 :: "l"(a), "f"(v.x), "f"(v.y), "f"(v.z), "f"(v.w) : "memory");
#else
    atomicAdd(a + 0, v.x);
    atomicAdd(a + 1, v.y);
    atomicAdd(a + 2, v.z);
    atomicAdd(a + 3, v.w);
#endif
    if (c == 0) atomicAdd(&g_deg[d], 1.0f);
}

// ================== kernel 3: fusion GEMM (HMMA, K=192 single shot) =======
#define ASTR_F 200   // 192+8; frag bank inc 4
#define BSTR_F 216   // 192+24; frag bank inc 12

__global__ __launch_bounds__(256) void k_fuse(
    const float* __restrict__ Wf, const float* __restrict__ bf,
    float* __restrict__ out, int nNodes)
{
    extern __shared__ char dyn[];
    __nv_bfloat16* sBhi = (__nv_bfloat16*)dyn;                    // 96*216
    __nv_bfloat16* sBlo = sBhi + 96 * BSTR_F;
    __nv_bfloat16* sAhi = sBlo + 96 * BSTR_F;                     // 128*200
    __nv_bfloat16* sAlo = sAhi + EM * ASTR_F;
    __shared__ float sinv[EM];

    const int t = threadIdx.x;
    const int lane = t & 31, wid = t >> 5;
    const int wm = wid & 3, wn = wid >> 2;
    const int gp = lane >> 2, tg = lane & 3;
    const int n0 = blockIdx.x * EM;

    if (t < EM) {
        int n = n0 + t;
        float d = (n < nNodes) ? g_deg[n] : 1.f;
        sinv[t] = 1.0f / fmaxf(d, 1.0f);
    }
    // stage B: pairs (2k2, 2k2+1) per n
    for (int i = t; i < 96 * 96; i += 256) {
        int n = i % 96, k2 = i / 96;
        float w0 = Wf[(2 * k2) * 96 + n];
        float w1 = Wf[(2 * k2 + 1) * 96 + n];
        uint32_t hi, lo;
        split2(w0, w1, hi, lo);
        *(uint32_t*)(sBhi + n * BSTR_F + 2 * k2) = hi;
        *(uint32_t*)(sBlo + n * BSTR_F + 2 * k2) = lo;
    }
    __syncthreads();   // sinv ready
    // stage A: row-major pairs; k2<48 from x_embed, k2>=48 from agg*sinv
    for (int i = t; i < EM * 96; i += 256) {
        int row = i / 96, k2 = i % 96;
        int gn = n0 + row;
        float v0 = 0.f, v1 = 0.f;
        if (gn < nNodes) {
            if (k2 < 48) {
                float2 e = *(const float2*)(&g_xemb[gn * 96 + 2 * k2]);
                v0 = e.x; v1 = e.y;
            } else {
                float2 a = *(const float2*)(&g_agg[gn * 96 + 2 * (k2 - 48)]);
                v0 = a.x * sinv[row]; v1 = a.y * sinv[row];
            }
        }
        uint32_t hi, lo;
        split2(v0, v1, hi, lo);
        *(uint32_t*)(sAhi + row * ASTR_F + 2 * k2) = hi;
        *(uint32_t*)(sAlo + row * ASTR_F + 2 * k2) = lo;
    }
    __syncthreads();

    float acc[2][6][4];
#pragma unroll
    for (int i = 0; i < 2; i++)
#pragma unroll
        for (int j = 0; j < 6; j++)
#pragma unroll
            for (int q = 0; q < 4; q++) acc[i][j][q] = 0.f;

#pragma unroll
    for (int s8 = 0; s8 < 12; s8++) {
        int k = s8 * 16;
        uint32_t ah[2][4], al[2][4], bh[6][2], bl[6][2];
#pragma unroll
        for (int ma = 0; ma < 2; ma++) {
            int r = wm * 32 + ma * 16 + gp;
            const __nv_bfloat16* p0 = sAhi + r * ASTR_F + k + tg * 2;
            const __nv_bfloat16* p1 = sAlo + r * ASTR_F + k + tg * 2;
            ah[ma][0] = *(uint32_t*)(p0);
            ah[ma][1] = *(uint32_t*)(p0 + 8 * ASTR_F);
            ah[ma][2] = *(uint32_t*)(p0 + 8);
            ah[ma][3] = *(uint32_t*)(p0 + 8 * ASTR_F + 8);
            al[ma][0] = *(uint32_t*)(p1);
            al[ma][1] = *(uint32_t*)(p1 + 8 * ASTR_F);
            al[ma][2] = *(uint32_t*)(p1 + 8);
            al[ma][3] = *(uint32_t*)(p1 + 8 * ASTR_F + 8);
        }
#pragma unroll
        for (int nb = 0; nb < 6; nb++) {
            int n = wn * 48 + nb * 8 + gp;
            const __nv_bfloat16* q0 = sBhi + n * BSTR_F + k + tg * 2;
            const __nv_bfloat16* q1 = sBlo + n * BSTR_F + k + tg * 2;
            bh[nb][0] = *(uint32_t*)(q0);
            bh[nb][1] = *(uint32_t*)(q0 + 8);
            bl[nb][0] = *(uint32_t*)(q1);
            bl[nb][1] = *(uint32_t*)(q1 + 8);
        }
#pragma unroll
        for (int ma = 0; ma < 2; ma++)
#pragma unroll
            for (int nb = 0; nb < 6; nb++) {
                mma_bf16(acc[ma][nb], ah[ma], bh[nb]);
                mma_bf16(acc[ma][nb], al[ma], bh[nb]);
                mma_bf16(acc[ma][nb], ah[ma], bl[nb]);
            }
    }

#pragma unroll
    for (int ma = 0; ma < 2; ma++) {
        int r0 = n0 + wm * 32 + ma * 16 + gp;
#pragma unroll
        for (int half = 0; half < 2; half++) {
            int r = r0 + half * 8;
            if (r < nNodes) {
#pragma unroll
                for (int nb = 0; nb < 6; nb++) {
                    int col = wn * 48 + nb * 8 + tg * 2;
                    float2 v;
                    v.x = acc[ma][nb][half * 2 + 0] + bf[col];
                    v.y = acc[ma][nb][half * 2 + 1] + bf[col + 1];
                    *(float2*)(&out[r * 96 + col]) = v;
                }
            }
        }
    }
}

// ---------------- kernel 3.5: BN stats over fused output ------------------
__global__ __launch_bounds__(384) void k_stats(const float* __restrict__ out, int nNodes)
{
    __shared__ float ss[FF], sq[FF];
    int t = threadIdx.x;
    int c = t % FF, g = t / FF;   // g in 0..3
    if (t < FF) { ss[t] = 0.f; sq[t] = 0.f; }
    __syncthreads();
    float a = 0.f, b = 0.f;
    for (int r = blockIdx.x * 4 + g; r < nNodes; r += gridDim.x * 4) {
        float v = out[r * FF + c];
        a += v; b += v * v;
    }
    atomicAdd(&ss[c], a);
    atomicAdd(&sq[c], b);
    __syncthreads();
    if (t < FF) {
        atomicAdd(&g_sum[t], ss[t]);
        atomicAdd(&g_sq[t], sq[t]);
    }
}

// ---------------- kernel 4: BatchNorm + exact GELU (in-place, float4) -----
__global__ __launch_bounds__(256) void k_bn(
    float* __restrict__ out, const float* __restrict__ gamma,
    const float* __restrict__ beta, int nNodes)
{
    __shared__ float sscale[FF], sshift[FF];
    if (threadIdx.x < FF) {
        int f = threadIdx.x;
        float invN = 1.0f / (float)nNodes;
        float mean = g_sum[f] * invN;
        float var = g_sq[f] * invN - mean * mean;
        float rs = rsqrtf(var + 1e-5f);
        float sc = rs * gamma[f];
        sscale[f] = sc;
        sshift[f] = beta[f] - mean * sc;
    }
    __syncthreads();
    int total4 = nNodes * (FF / 4);
    int idx = blockIdx.x * blockDim.x + threadIdx.x;
    int stride = gridDim.x * blockDim.x;
    for (int i = idx; i < total4; i += stride) {
        int f4 = (i % 24) * 4;
        float4 v = ((float4*)out)[i];
        float r[4] = {v.x, v.y, v.z, v.w};
#pragma unroll
        for (int j = 0; j < 4; j++) {
            float y = r[j] * sscale[f4 + j] + sshift[f4 + j];
            r[j] = 0.5f * y * (1.0f + erff(y * 0.70710678118654752f));
        }
        ((float4*)out)[i] = make_float4(r[0], r[1], r[2], r[3]);
    }
}

// ---------------- launch ----------------
extern "C" void kernel_launch(void* const* d_in, const int* in_sizes, int n_in,
                              void* d_out, int out_size)
{
    const float* x      = (const float*)d_in[0];
    const float* B      = (const float*)d_in[1];
    const float* Wp     = (const float*)d_in[2];
    const float* bp     = (const float*)d_in[3];
    const float* Wf     = (const float*)d_in[4];
    const float* bf     = (const float*)d_in[5];
    const float* gamma  = (const float*)d_in[6];
    const float* beta   = (const float*)d_in[7];
    const void* ei      = d_in[8];

    int nNodes = in_sizes[0] / 3;
    int E = in_sizes[8] / 2;
    int nTiles = (nNodes + EM - 1) / EM;

    const int smem_embed = (96 * BSTR_E * 2 + EM * ASTR_E * 2) * 2;  // 177,152 B
    const int smem_fuse  = (96 * BSTR_F * 2 + EM * ASTR_F * 2) * 2;  // 185,344 B
    cudaFuncSetAttribute(k_embed, cudaFuncAttributeMaxDynamicSharedMemorySize, smem_embed);
    cudaFuncSetAttribute(k_fuse,  cudaFuncAttributeMaxDynamicSharedMemorySize, smem_fuse);

    k_zero<<<4096, 256>>>(nNodes * FF, nNodes);
    k_embed<<<nTiles, 256, smem_embed>>>(x, B, Wp, bp, nNodes);
    {
        int total = E * 24;
        k_scatter<<<(total + 255) / 256, 256>>>(ei, E);
    }
    k_fuse<<<nTiles, 256, smem_fuse>>>(Wf, bf, (float*)d_out, nNodes);
    k_stats<<<256, 384>>>((const float*)d_out, nNodes);
    {
        int total4 = nNodes * (FF / 4);
        k_bn<<<(total4 + 1023) / 1024, 256>>>((float*)d_out, gamma, beta, nNodes);
    }
}

// round 11
// speedup vs baseline: 2.2284x; 1.2258x over previous
#include <cuda_runtime.h>
#include <cuda_bf16.h>
#include <math.h>
#include <stdint.h>

#define NN 50000
#define FF 96
#define EM 128   // nodes per GEMM CTA (tile M)

// ---------------- scratch (device globals; no allocation allowed) ----------
__device__ float g_xemb[NN * FF];
__device__ float g_agg[NN * FF];
__device__ float g_deg[NN];
__device__ float g_sum[FF];
__device__ float g_sq[FF];
// packed fragment-order weights: [kstep][n_atom][lane] -> {bh0, bh1, bl0, bl1}
__device__ uint4 g_BpE[16 * 12 * 32];   // embed: K=256 -> 16 ksteps, 12 n-atoms
__device__ uint4 g_BpF[12 * 12 * 32];   // fuse:  K=192 -> 12 ksteps, 12 n-atoms

// ---------------- helpers -------------------------------------------------
__device__ __forceinline__ uint32_t pack_bf16(float a, float b) {
    __nv_bfloat162 h = __floats2bfloat162_rn(a, b);
    return *(uint32_t*)&h;
}
__device__ __forceinline__ void split2(float a, float b, uint32_t& hi, uint32_t& lo) {
    __nv_bfloat16 ha = __float2bfloat16(a);
    __nv_bfloat16 hb = __float2bfloat16(b);
    float la = a - __bfloat162float(ha);
    float lb = b - __bfloat162float(hb);
    __nv_bfloat162 hh; hh.x = ha; hh.y = hb;
    hi = *(uint32_t*)&hh;
    lo = pack_bf16(la, lb);
}
__device__ __forceinline__ void mma_bf16(float* d, const uint32_t* a, const uint32_t* b) {
    asm volatile(
        "mma.sync.aligned.m16n8k16.row.col.f32.bf16.bf16.f32 "
        "{%0,%1,%2,%3}, {%4,%5,%6,%7}, {%8,%9}, {%0,%1,%2,%3};"
        : "+f"(d[0]), "+f"(d[1]), "+f"(d[2]), "+f"(d[3])
        : "r"(a[0]), "r"(a[1]), "r"(a[2]), "r"(a[3]), "r"(b[0]), "r"(b[1]));
}

// ---------------- kernel 0: zero scratch ----------------
__global__ void k_zero(int nAgg, int nDeg) {
    int idx = blockIdx.x * blockDim.x + threadIdx.x;
    int stride = gridDim.x * blockDim.x;
    for (int i = idx; i < nAgg; i += stride) g_agg[i] = 0.f;
    for (int i = idx; i < nDeg; i += stride) g_deg[i] = 0.f;
    if (idx < FF) { g_sum[idx] = 0.f; g_sq[idx] = 0.f; }
}

// ---------------- kernel 0.5: pack weights into fragment order ------------
// Embed K-order: k = 2m + (0:cos from Wp[m], 1:sin from Wp[128+m]).
// Fragment (m16n8k16 B, row.col): lane(gp=lane>>2, tg=lane&3):
//   b0 = cols (16s+2tg, +1), b1 = cols (16s+8+2tg, +1), row n = natom*8+gp.
__global__ void k_prepB(const float* __restrict__ Wp, const float* __restrict__ Wf) {
    int idx = blockIdx.x * blockDim.x + threadIdx.x;
    if (idx < 16 * 12 * 32) {
        int lane = idx & 31, nb = (idx >> 5) % 12, s = idx / (12 * 32);
        int gp = lane >> 2, tg = lane & 3;
        int n = nb * 8 + gp;
        int m0 = 8 * s + tg;        // k-pair (16s+2tg, +1) = (cos,sin) of m0
        int m1 = 8 * s + 4 + tg;    // k-pair (16s+8+2tg, +1)
        uint32_t h0, l0, h1, l1;
        split2(Wp[m0 * 96 + n], Wp[(128 + m0) * 96 + n], h0, l0);
        split2(Wp[m1 * 96 + n], Wp[(128 + m1) * 96 + n], h1, l1);
        g_BpE[idx] = make_uint4(h0, h1, l0, l1);
    }
    if (idx < 12 * 12 * 32) {
        int lane = idx & 31, nb = (idx >> 5) % 12, s = idx / (12 * 32);
        int gp = lane >> 2, tg = lane & 3;
        int n = nb * 8 + gp;
        int k0 = 16 * s + 2 * tg;
        int k1 = k0 + 8;
        uint32_t h0, l0, h1, l1;
        split2(Wf[k0 * 96 + n], Wf[(k0 + 1) * 96 + n], h0, l0);
        split2(Wf[k1 * 96 + n], Wf[(k1 + 1) * 96 + n], h1, l1);
        g_BpF[idx] = make_uint4(h0, h1, l0, l1);
    }
}

// ================== kernel 1: Fourier embed + projection (HMMA) ===========
// A in smem only (2 K-chunks of 128); B fragments streamed from g_BpE (L2).
#define ASTR_E 136   // A chunk stride (128+8) elem; frag bank inc 4

__global__ __launch_bounds__(256, 2) void k_embed(
    const float* __restrict__ x, const float* __restrict__ B,
    const float* __restrict__ bp, int nNodes)
{
    extern __shared__ char dyn[];
    __nv_bfloat16* sAhi = (__nv_bfloat16*)dyn;            // 128*136
    __nv_bfloat16* sAlo = sAhi + EM * ASTR_E;             // total 69,632 B
    __shared__ float sx[EM][3];
    __shared__ float sb[384];

    const int t = threadIdx.x;
    const int lane = t & 31, wid = t >> 5;
    const int wm = wid & 3, wn = wid >> 2;       // warp grid 4(M) x 2(N)
    const int gp = lane >> 2, tg = lane & 3;
    const int n0 = blockIdx.x * EM;

    for (int i = t; i < 384; i += 256) sb[i] = B[i];
    for (int i = t; i < EM * 3; i += 256) {
        int n = n0 + i / 3;
        sx[i / 3][i % 3] = (n < nNodes) ? x[n * 3 + (i % 3)] : 0.f;
    }

    float acc[2][6][4];
#pragma unroll
    for (int i = 0; i < 2; i++)
#pragma unroll
        for (int j = 0; j < 6; j++)
#pragma unroll
            for (int q = 0; q < 4; q++) acc[i][j][q] = 0.f;

    const float TWO_PI = 6.283185307179586f;

    for (int c = 0; c < 2; c++) {
        __syncthreads();
        // stage A chunk: 128 nodes x 64 m -> local cols (2j, 2j+1)
        for (int i = t; i < EM * 64; i += 256) {
            int n = i >> 6, j = i & 63;
            int m = c * 64 + j;
            float a = sx[n][0] * sb[m] + sx[n][1] * sb[128 + m] + sx[n][2] * sb[256 + m];
            a *= TWO_PI;
            float sv, cv;
            sincosf(a, &sv, &cv);
            uint32_t hi, lo;
            split2(cv, sv, hi, lo);
            *(uint32_t*)(sAhi + n * ASTR_E + 2 * j) = hi;
            *(uint32_t*)(sAlo + n * ASTR_E + 2 * j) = lo;
        }
        __syncthreads();

#pragma unroll
        for (int s8 = 0; s8 < 8; s8++) {
            int kl = s8 * 16;            // A local k
            int S = c * 8 + s8;          // global kstep
            uint32_t ah[2][4], al[2][4], bh[6][2], bl[6][2];
#pragma unroll
            for (int nb = 0; nb < 6; nb++) {
                uint4 b = g_BpE[(S * 12 + wn * 6 + nb) * 32 + lane];
                bh[nb][0] = b.x; bh[nb][1] = b.y;
                bl[nb][0] = b.z; bl[nb][1] = b.w;
            }
#pragma unroll
            for (int ma = 0; ma < 2; ma++) {
                int r = wm * 32 + ma * 16 + gp;
                const __nv_bfloat16* p0 = sAhi + r * ASTR_E + kl + tg * 2;
                const __nv_bfloat16* p1 = sAlo + r * ASTR_E + kl + tg * 2;
                ah[ma][0] = *(uint32_t*)(p0);
                ah[ma][1] = *(uint32_t*)(p0 + 8 * ASTR_E);
                ah[ma][2] = *(uint32_t*)(p0 + 8);
                ah[ma][3] = *(uint32_t*)(p0 + 8 * ASTR_E + 8);
                al[ma][0] = *(uint32_t*)(p1);
                al[ma][1] = *(uint32_t*)(p1 + 8 * ASTR_E);
                al[ma][2] = *(uint32_t*)(p1 + 8);
                al[ma][3] = *(uint32_t*)(p1 + 8 * ASTR_E + 8);
            }
#pragma unroll
            for (int ma = 0; ma < 2; ma++)
#pragma unroll
                for (int nb = 0; nb < 6; nb++) {
                    mma_bf16(acc[ma][nb], ah[ma], bh[nb]);
                    mma_bf16(acc[ma][nb], al[ma], bh[nb]);
                    mma_bf16(acc[ma][nb], ah[ma], bl[nb]);
                }
        }
    }

#pragma unroll
    for (int ma = 0; ma < 2; ma++) {
        int r0 = n0 + wm * 32 + ma * 16 + gp;
#pragma unroll
        for (int half = 0; half < 2; half++) {
            int r = r0 + half * 8;
            if (r < nNodes) {
#pragma unroll
                for (int nb = 0; nb < 6; nb++) {
                    int col = wn * 48 + nb * 8 + tg * 2;
                    float2 v;
                    v.x = acc[ma][nb][half * 2 + 0] + bp[col];
                    v.y = acc[ma][nb][half * 2 + 1] + bp[col + 1];
                    *(float2*)(&g_xemb[r * 96 + col]) = v;
                }
            }
        }
    }
}

// ---------------- kernel 2: edge scatter (sum + degree) ----------------
__global__ __launch_bounds__(256) void k_scatter(const void* __restrict__ ei, int E)
{
    int idx = blockIdx.x * blockDim.x + threadIdx.x;
    int total = E * 24;
    if (idx >= total) return;
    int e = idx / 24, c = idx % 24;

    const int* e32 = (const int*)ei;
    bool is64 = (e32[1] == 0) & (e32[3] == 0) & (e32[5] == 0) & (e32[7] == 0);

    int s, d;
    if (is64) {
        const long long* e64 = (const long long*)ei;
        s = (int)e64[e];
        d = (int)e64[E + e];
    } else {
        s = e32[e];
        d = e32[E + e];
    }
    const float4 v = *(const float4*)(&g_xemb[s * 96 + c * 4]);
    float* a = &g_agg[d * 96 + c * 4];
#if __CUDA_ARCH__ >= 900
    asm volatile("red.global.add.v4.f32 [%0], {%1, %2, %3, %4};"
                 :: "l"(a), "f"(v.x), "f"(v.y), "f"(v.z), "f"(v.w) : "memory");
#else
    atomicAdd(a + 0, v.x);
    atomicAdd(a + 1, v.y);
    atomicAdd(a + 2, v.z);
    atomicAdd(a + 3, v.w);
#endif
    if (c == 0) atomicAdd(&g_deg[d], 1.0f);
}

// ================== kernel 3: fusion GEMM (HMMA, K=192) ===================
#define ASTR_F 200   // 192+8; frag bank inc 4

__global__ __launch_bounds__(256, 2) void k_fuse(
    const float* __restrict__ bf, float* __restrict__ out, int nNodes)
{
    extern __shared__ char dyn[];
    __nv_bfloat16* sAhi = (__nv_bfloat16*)dyn;            // 128*200
    __nv_bfloat16* sAlo = sAhi + EM * ASTR_F;             // total 102,400 B
    __shared__ float sinv[EM];

    const int t = threadIdx.x;
    const int lane = t & 31, wid = t >> 5;
    const int wm = wid & 3, wn = wid >> 2;
    const int gp = lane >> 2, tg = lane & 3;
    const int n0 = blockIdx.x * EM;

    if (t < EM) {
        int n = n0 + t;
        float d = (n < nNodes) ? g_deg[n] : 1.f;
        sinv[t] = 1.0f / fmaxf(d, 1.0f);
    }
    __syncthreads();   // sinv ready
    // stage A: pairs; k2<48 from x_embed, k2>=48 from agg*sinv
    for (int i = t; i < EM * 96; i += 256) {
        int row = i / 96, k2 = i % 96;
        int gn = n0 + row;
        float v0 = 0.f, v1 = 0.f;
        if (gn < nNodes) {
            if (k2 < 48) {
                float2 e = *(const float2*)(&g_xemb[gn * 96 + 2 * k2]);
                v0 = e.x; v1 = e.y;
            } else {
                float2 a = *(const float2*)(&g_agg[gn * 96 + 2 * (k2 - 48)]);
                v0 = a.x * sinv[row]; v1 = a.y * sinv[row];
            }
        }
        uint32_t hi, lo;
        split2(v0, v1, hi, lo);
        *(uint32_t*)(sAhi + row * ASTR_F + 2 * k2) = hi;
        *(uint32_t*)(sAlo + row * ASTR_F + 2 * k2) = lo;
    }
    __syncthreads();

    float acc[2][6][4];
#pragma unroll
    for (int i = 0; i < 2; i++)
#pragma unroll
        for (int j = 0; j < 6; j++)
#pragma unroll
            for (int q = 0; q < 4; q++) acc[i][j][q] = 0.f;

#pragma unroll
    for (int s8 = 0; s8 < 12; s8++) {
        int k = s8 * 16;
        uint32_t ah[2][4], al[2][4], bh[6][2], bl[6][2];
#pragma unroll
        for (int nb = 0; nb < 6; nb++) {
            uint4 b = g_BpF[(s8 * 12 + wn * 6 + nb) * 32 + lane];
            bh[nb][0] = b.x; bh[nb][1] = b.y;
            bl[nb][0] = b.z; bl[nb][1] = b.w;
        }
#pragma unroll
        for (int ma = 0; ma < 2; ma++) {
            int r = wm * 32 + ma * 16 + gp;
            const __nv_bfloat16* p0 = sAhi + r * ASTR_F + k + tg * 2;
            const __nv_bfloat16* p1 = sAlo + r * ASTR_F + k + tg * 2;
            ah[ma][0] = *(uint32_t*)(p0);
            ah[ma][1] = *(uint32_t*)(p0 + 8 * ASTR_F);
            ah[ma][2] = *(uint32_t*)(p0 + 8);
            ah[ma][3] = *(uint32_t*)(p0 + 8 * ASTR_F + 8);
            al[ma][0] = *(uint32_t*)(p1);
            al[ma][1] = *(uint32_t*)(p1 + 8 * ASTR_F);
            al[ma][2] = *(uint32_t*)(p1 + 8);
            al[ma][3] = *(uint32_t*)(p1 + 8 * ASTR_F + 8);
        }
#pragma unroll
        for (int ma = 0; ma < 2; ma++)
#pragma unroll
            for (int nb = 0; nb < 6; nb++) {
                mma_bf16(acc[ma][nb], ah[ma], bh[nb]);
                mma_bf16(acc[ma][nb], al[ma], bh[nb]);
                mma_bf16(acc[ma][nb], ah[ma], bl[nb]);
            }
    }

#pragma unroll
    for (int ma = 0; ma < 2; ma++) {
        int r0 = n0 + wm * 32 + ma * 16 + gp;
#pragma unroll
        for (int half = 0; half < 2; half++) {
            int r = r0 + half * 8;
            if (r < nNodes) {
#pragma unroll
                for (int nb = 0; nb < 6; nb++) {
                    int col = wn * 48 + nb * 8 + tg * 2;
                    float2 v;
                    v.x = acc[ma][nb][half * 2 + 0] + bf[col];
                    v.y = acc[ma][nb][half * 2 + 1] + bf[col + 1];
                    *(float2*)(&out[r * 96 + col]) = v;
                }
            }
        }
    }
}

// ---------------- kernel 3.5: BN stats over fused output ------------------
__global__ __launch_bounds__(384) void k_stats(const float* __restrict__ out, int nNodes)
{
    __shared__ float ss[FF], sq[FF];
    int t = threadIdx.x;
    int c = t % FF, g = t / FF;
    if (t < FF) { ss[t] = 0.f; sq[t] = 0.f; }
    __syncthreads();
    float a = 0.f, b = 0.f;
    for (int r = blockIdx.x * 4 + g; r < nNodes; r += gridDim.x * 4) {
        float v = out[r * FF + c];
        a += v; b += v * v;
    }
    atomicAdd(&ss[c], a);
    atomicAdd(&sq[c], b);
    __syncthreads();
    if (t < FF) {
        atomicAdd(&g_sum[t], ss[t]);
        atomicAdd(&g_sq[t], sq[t]);
    }
}

// ---------------- kernel 4: BatchNorm + exact GELU (in-place, float4) -----
__global__ __launch_bounds__(256) void k_bn(
    float* __restrict__ out, const float* __restrict__ gamma,
    const float* __restrict__ beta, int nNodes)
{
    __shared__ float sscale[FF], sshift[FF];
    if (threadIdx.x < FF) {
        int f = threadIdx.x;
        float invN = 1.0f / (float)nNodes;
        float mean = g_sum[f] * invN;
        float var = g_sq[f] * invN - mean * mean;
        float rs = rsqrtf(var + 1e-5f);
        float sc = rs * gamma[f];
        sscale[f] = sc;
        sshift[f] = beta[f] - mean * sc;
    }
    __syncthreads();
    int total4 = nNodes * (FF / 4);
    int idx = blockIdx.x * blockDim.x + threadIdx.x;
    int stride = gridDim.x * blockDim.x;
    for (int i = idx; i < total4; i += stride) {
        int f4 = (i % 24) * 4;
        float4 v = ((float4*)out)[i];
        float r[4] = {v.x, v.y, v.z, v.w};
#pragma unroll
        for (int j = 0; j < 4; j++) {
            float y = r[j] * sscale[f4 + j] + sshift[f4 + j];
            r[j] = 0.5f * y * (1.0f + erff(y * 0.70710678118654752f));
        }
        ((float4*)out)[i] = make_float4(r[0], r[1], r[2], r[3]);
    }
}

// ---------------- launch ----------------
extern "C" void kernel_launch(void* const* d_in, const int* in_sizes, int n_in,
                              void* d_out, int out_size)
{
    const float* x      = (const float*)d_in[0];
    const float* B      = (const float*)d_in[1];
    const float* Wp     = (const float*)d_in[2];
    const float* bp     = (const float*)d_in[3];
    const float* Wf     = (const float*)d_in[4];
    const float* bf     = (const float*)d_in[5];
    const float* gamma  = (const float*)d_in[6];
    const float* beta   = (const float*)d_in[7];
    const void* ei      = d_in[8];

    int nNodes = in_sizes[0] / 3;
    int E = in_sizes[8] / 2;
    int nTiles = (nNodes + EM - 1) / EM;

    const int smem_embed = EM * ASTR_E * 2 * 2;   // 69,632 B
    const int smem_fuse  = EM * ASTR_F * 2 * 2;   // 102,400 B
    cudaFuncSetAttribute(k_embed, cudaFuncAttributeMaxDynamicSharedMemorySize, smem_embed);
    cudaFuncSetAttribute(k_fuse,  cudaFuncAttributeMaxDynamicSharedMemorySize, smem_fuse);

    k_zero<<<4096, 256>>>(nNodes * FF, nNodes);
    k_prepB<<<(16 * 12 * 32 + 255) / 256, 256>>>(Wp, Wf);
    k_embed<<<nTiles, 256, smem_embed>>>(x, B, bp, nNodes);
    {
        int total = E * 24;
        k_scatter<<<(total + 255) / 256, 256>>>(ei, E);
    }
    k_fuse<<<nTiles, 256, smem_fuse>>>(bf, (float*)d_out, nNodes);
    k_stats<<<256, 384>>>((const float*)d_out, nNodes);
    {
        int total4 = nNodes * (FF / 4);
        k_bn<<<(total4 + 1023) / 1024, 256>>>((float*)d_out, gamma, beta, nNodes);
    }
}

// round 12
// speedup vs baseline: 2.5592x; 1.1484x over previous
#include <cuda_runtime.h>
#include <cuda_bf16.h>
#include <math.h>
#include <stdint.h>

#define NN 50000
#define FF 96
#define EM 128   // nodes per GEMM CTA (tile M)
#define EE 800000

// ---------------- scratch (device globals; no allocation allowed) ----------
__device__ float g_xemb[NN * FF];
__device__ float g_agg[NN * FF];     // holds MEAN after k_gather
__device__ float g_sum[FF];
__device__ float g_sq[FF];
// CSR machinery
__device__ int g_degi[NN];
__device__ int g_start[NN];
__device__ int g_cursor[NN];
__device__ int g_srcs[EE];
__device__ int g_blocksum[256];
__device__ int g_blockoff[256];
// packed fragment-order weights: [kstep][n_atom][lane] -> {bh0, bh1, bl0, bl1}
__device__ uint4 g_BpE[16 * 12 * 32];
__device__ uint4 g_BpF[12 * 12 * 32];

// ---------------- helpers -------------------------------------------------
__device__ __forceinline__ uint32_t pack_bf16(float a, float b) {
    __nv_bfloat162 h = __floats2bfloat162_rn(a, b);
    return *(uint32_t*)&h;
}
__device__ __forceinline__ void split2(float a, float b, uint32_t& hi, uint32_t& lo) {
    __nv_bfloat16 ha = __float2bfloat16(a);
    __nv_bfloat16 hb = __float2bfloat16(b);
    float la = a - __bfloat162float(ha);
    float lb = b - __bfloat162float(hb);
    __nv_bfloat162 hh; hh.x = ha; hh.y = hb;
    hi = *(uint32_t*)&hh;
    lo = pack_bf16(la, lb);
}
__device__ __forceinline__ void mma_bf16(float* d, const uint32_t* a, const uint32_t* b) {
    asm volatile(
        "mma.sync.aligned.m16n8k16.row.col.f32.bf16.bf16.f32 "
        "{%0,%1,%2,%3}, {%4,%5,%6,%7}, {%8,%9}, {%0,%1,%2,%3};"
        : "+f"(d[0]), "+f"(d[1]), "+f"(d[2]), "+f"(d[3])
        : "r"(a[0]), "r"(a[1]), "r"(a[2]), "r"(a[3]), "r"(b[0]), "r"(b[1]));
}
__device__ __forceinline__ bool edge_is64(const void* ei) {
    const int* e32 = (const int*)ei;
    return (e32[1] == 0) & (e32[3] == 0) & (e32[5] == 0) & (e32[7] == 0);
}
__device__ __forceinline__ int edge_at(const void* ei, bool is64, int idx) {
    return is64 ? (int)((const long long*)ei)[idx] : ((const int*)ei)[idx];
}

// ---------------- kernel 0: zero scratch ----------------
__global__ void k_zero(int nNodes) {
    int idx = blockIdx.x * blockDim.x + threadIdx.x;
    int stride = gridDim.x * blockDim.x;
    for (int i = idx; i < nNodes; i += stride) { g_degi[i] = 0; g_cursor[i] = 0; }
    if (idx < FF) { g_sum[idx] = 0.f; g_sq[idx] = 0.f; }
}

// ---------------- kernel 0.5: pack weights into fragment order ------------
__global__ void k_prepB(const float* __restrict__ Wp, const float* __restrict__ Wf) {
    int idx = blockIdx.x * blockDim.x + threadIdx.x;
    if (idx < 16 * 12 * 32) {
        int lane = idx & 31, nb = (idx >> 5) % 12, s = idx / (12 * 32);
        int gp = lane >> 2, tg = lane & 3;
        int n = nb * 8 + gp;
        int m0 = 8 * s + tg;
        int m1 = 8 * s + 4 + tg;
        uint32_t h0, l0, h1, l1;
        split2(Wp[m0 * 96 + n], Wp[(128 + m0) * 96 + n], h0, l0);
        split2(Wp[m1 * 96 + n], Wp[(128 + m1) * 96 + n], h1, l1);
        g_BpE[idx] = make_uint4(h0, h1, l0, l1);
    }
    if (idx < 12 * 12 * 32) {
        int lane = idx & 31, nb = (idx >> 5) % 12, s = idx / (12 * 32);
        int gp = lane >> 2, tg = lane & 3;
        int n = nb * 8 + gp;
        int k0 = 16 * s + 2 * tg;
        int k1 = k0 + 8;
        uint32_t h0, l0, h1, l1;
        split2(Wf[k0 * 96 + n], Wf[(k0 + 1) * 96 + n], h0, l0);
        split2(Wf[k1 * 96 + n], Wf[(k1 + 1) * 96 + n], h1, l1);
        g_BpF[idx] = make_uint4(h0, h1, l0, l1);
    }
}

// ================== kernel 1: Fourier embed + projection (HMMA) ===========
#define ASTR_E 136

__global__ __launch_bounds__(256, 2) void k_embed(
    const float* __restrict__ x, const float* __restrict__ B,
    const float* __restrict__ bp, int nNodes)
{
    extern __shared__ char dyn[];
    __nv_bfloat16* sAhi = (__nv_bfloat16*)dyn;
    __nv_bfloat16* sAlo = sAhi + EM * ASTR_E;
    __shared__ float sx[EM][3];
    __shared__ float sb[384];

    const int t = threadIdx.x;
    const int lane = t & 31, wid = t >> 5;
    const int wm = wid & 3, wn = wid >> 2;
    const int gp = lane >> 2, tg = lane & 3;
    const int n0 = blockIdx.x * EM;

    for (int i = t; i < 384; i += 256) sb[i] = B[i];
    for (int i = t; i < EM * 3; i += 256) {
        int n = n0 + i / 3;
        sx[i / 3][i % 3] = (n < nNodes) ? x[n * 3 + (i % 3)] : 0.f;
    }

    float acc[2][6][4];
#pragma unroll
    for (int i = 0; i < 2; i++)
#pragma unroll
        for (int j = 0; j < 6; j++)
#pragma unroll
            for (int q = 0; q < 4; q++) acc[i][j][q] = 0.f;

    const float TWO_PI = 6.283185307179586f;

    for (int c = 0; c < 2; c++) {
        __syncthreads();
        for (int i = t; i < EM * 64; i += 256) {
            int n = i >> 6, j = i & 63;
            int m = c * 64 + j;
            float a = sx[n][0] * sb[m] + sx[n][1] * sb[128 + m] + sx[n][2] * sb[256 + m];
            a *= TWO_PI;
            float sv, cv;
            sincosf(a, &sv, &cv);
            uint32_t hi, lo;
            split2(cv, sv, hi, lo);
            *(uint32_t*)(sAhi + n * ASTR_E + 2 * j) = hi;
            *(uint32_t*)(sAlo + n * ASTR_E + 2 * j) = lo;
        }
        __syncthreads();

#pragma unroll
        for (int s8 = 0; s8 < 8; s8++) {
            int kl = s8 * 16;
            int S = c * 8 + s8;
            uint32_t ah[2][4], al[2][4], bh[6][2], bl[6][2];
#pragma unroll
            for (int nb = 0; nb < 6; nb++) {
                uint4 b = g_BpE[(S * 12 + wn * 6 + nb) * 32 + lane];
                bh[nb][0] = b.x; bh[nb][1] = b.y;
                bl[nb][0] = b.z; bl[nb][1] = b.w;
            }
#pragma unroll
            for (int ma = 0; ma < 2; ma++) {
                int r = wm * 32 + ma * 16 + gp;
                const __nv_bfloat16* p0 = sAhi + r * ASTR_E + kl + tg * 2;
                const __nv_bfloat16* p1 = sAlo + r * ASTR_E + kl + tg * 2;
                ah[ma][0] = *(uint32_t*)(p0);
                ah[ma][1] = *(uint32_t*)(p0 + 8 * ASTR_E);
                ah[ma][2] = *(uint32_t*)(p0 + 8);
                ah[ma][3] = *(uint32_t*)(p0 + 8 * ASTR_E + 8);
                al[ma][0] = *(uint32_t*)(p1);
                al[ma][1] = *(uint32_t*)(p1 + 8 * ASTR_E);
                al[ma][2] = *(uint32_t*)(p1 + 8);
                al[ma][3] = *(uint32_t*)(p1 + 8 * ASTR_E + 8);
            }
#pragma unroll
            for (int ma = 0; ma < 2; ma++)
#pragma unroll
                for (int nb = 0; nb < 6; nb++) {
                    mma_bf16(acc[ma][nb], ah[ma], bh[nb]);
                    mma_bf16(acc[ma][nb], al[ma], bh[nb]);
                    mma_bf16(acc[ma][nb], ah[ma], bl[nb]);
                }
        }
    }

#pragma unroll
    for (int ma = 0; ma < 2; ma++) {
        int r0 = n0 + wm * 32 + ma * 16 + gp;
#pragma unroll
        for (int half = 0; half < 2; half++) {
            int r = r0 + half * 8;
            if (r < nNodes) {
#pragma unroll
                for (int nb = 0; nb < 6; nb++) {
                    int col = wn * 48 + nb * 8 + tg * 2;
                    float2 v;
                    v.x = acc[ma][nb][half * 2 + 0] + bp[col];
                    v.y = acc[ma][nb][half * 2 + 1] + bp[col + 1];
                    *(float2*)(&g_xemb[r * 96 + col]) = v;
                }
            }
        }
    }
}

// ================== CSR build ==============================================
__global__ __launch_bounds__(256) void k_hist(const void* __restrict__ ei, int E) {
    int e = blockIdx.x * blockDim.x + threadIdx.x;
    if (e >= E) return;
    bool is64 = edge_is64(ei);
    int d = edge_at(ei, is64, E + e);
    atomicAdd(&g_degi[d], 1);
}

__global__ __launch_bounds__(256) void k_s1(int nNodes) {
    __shared__ int sc[256];
    int i = blockIdx.x * 256 + threadIdx.x;
    sc[threadIdx.x] = (i < nNodes) ? g_degi[i] : 0;
    __syncthreads();
    for (int off = 128; off > 0; off >>= 1) {
        if (threadIdx.x < off) sc[threadIdx.x] += sc[threadIdx.x + off];
        __syncthreads();
    }
    if (threadIdx.x == 0) g_blocksum[blockIdx.x] = sc[0];
}

__global__ __launch_bounds__(256) void k_s2(int nBlocks) {
    __shared__ int sc[256];
    int t = threadIdx.x;
    int v = (t < nBlocks) ? g_blocksum[t] : 0;
    sc[t] = v;
    __syncthreads();
    for (int off = 1; off < 256; off <<= 1) {
        int x = (t >= off) ? sc[t - off] : 0;
        __syncthreads();
        sc[t] += x;
        __syncthreads();
    }
    if (t < nBlocks) g_blockoff[t] = sc[t] - v;   // exclusive
}

__global__ __launch_bounds__(256) void k_s3(int nNodes) {
    __shared__ int sc[256];
    int t = threadIdx.x;
    int i = blockIdx.x * 256 + t;
    int v = (i < nNodes) ? g_degi[i] : 0;
    sc[t] = v;
    __syncthreads();
    for (int off = 1; off < 256; off <<= 1) {
        int x = (t >= off) ? sc[t - off] : 0;
        __syncthreads();
        sc[t] += x;
        __syncthreads();
    }
    if (i < nNodes) g_start[i] = g_blockoff[blockIdx.x] + sc[t] - v;
}

__global__ __launch_bounds__(256) void k_fill(const void* __restrict__ ei, int E) {
    int e = blockIdx.x * blockDim.x + threadIdx.x;
    if (e >= E) return;
    bool is64 = edge_is64(ei);
    int s = edge_at(ei, is64, e);
    int d = edge_at(ei, is64, E + e);
    int pos = g_start[d] + atomicAdd(&g_cursor[d], 1);
    g_srcs[pos] = s;
}

// ================== kernel 2: gather mean (warp per node) ==================
__global__ __launch_bounds__(256) void k_gather(int nNodes) {
    int warp = (blockIdx.x * blockDim.x + threadIdx.x) >> 5;
    int lane = threadIdx.x & 31;
    if (warp >= nNodes) return;
    int deg = g_degi[warp];
    int start = g_start[warp];
    float4 acc = make_float4(0.f, 0.f, 0.f, 0.f);
    for (int base = 0; base < deg; base += 32) {
        int eid = base + lane;
        int s_l = (eid < deg) ? g_srcs[start + eid] : 0;
        int cnt = min(32, deg - base);
        for (int i = 0; i < cnt; i++) {
            int s = __shfl_sync(0xffffffffu, s_l, i);
            if (lane < 24) {
                float4 v = *(const float4*)(&g_xemb[s * 96 + lane * 4]);
                acc.x += v.x; acc.y += v.y; acc.z += v.z; acc.w += v.w;
            }
        }
    }
    if (lane < 24) {
        float inv = 1.0f / (float)max(deg, 1);
        acc.x *= inv; acc.y *= inv; acc.z *= inv; acc.w *= inv;
        *(float4*)(&g_agg[warp * 96 + lane * 4]) = acc;
    }
}

// ================== kernel 3: fusion GEMM (HMMA, K=192) ===================
#define ASTR_F 200

__global__ __launch_bounds__(256, 2) void k_fuse(
    const float* __restrict__ bf, float* __restrict__ out, int nNodes)
{
    extern __shared__ char dyn[];
    __nv_bfloat16* sAhi = (__nv_bfloat16*)dyn;
    __nv_bfloat16* sAlo = sAhi + EM * ASTR_F;

    const int t = threadIdx.x;
    const int lane = t & 31, wid = t >> 5;
    const int wm = wid & 3, wn = wid >> 2;
    const int gp = lane >> 2, tg = lane & 3;
    const int n0 = blockIdx.x * EM;

    // stage A: pairs; k2<48 from x_embed, k2>=48 from agg (already mean)
    for (int i = t; i < EM * 96; i += 256) {
        int row = i / 96, k2 = i % 96;
        int gn = n0 + row;
        float v0 = 0.f, v1 = 0.f;
        if (gn < nNodes) {
            if (k2 < 48) {
                float2 e = *(const float2*)(&g_xemb[gn * 96 + 2 * k2]);
                v0 = e.x; v1 = e.y;
            } else {
                float2 a = *(const float2*)(&g_agg[gn * 96 + 2 * (k2 - 48)]);
                v0 = a.x; v1 = a.y;
            }
        }
        uint32_t hi, lo;
        split2(v0, v1, hi, lo);
        *(uint32_t*)(sAhi + row * ASTR_F + 2 * k2) = hi;
        *(uint32_t*)(sAlo + row * ASTR_F + 2 * k2) = lo;
    }
    __syncthreads();

    float acc[2][6][4];
#pragma unroll
    for (int i = 0; i < 2; i++)
#pragma unroll
        for (int j = 0; j < 6; j++)
#pragma unroll
            for (int q = 0; q < 4; q++) acc[i][j][q] = 0.f;

#pragma unroll
    for (int s8 = 0; s8 < 12; s8++) {
        int k = s8 * 16;
        uint32_t ah[2][4], al[2][4], bh[6][2], bl[6][2];
#pragma unroll
        for (int nb = 0; nb < 6; nb++) {
            uint4 b = g_BpF[(s8 * 12 + wn * 6 + nb) * 32 + lane];
            bh[nb][0] = b.x; bh[nb][1] = b.y;
            bl[nb][0] = b.z; bl[nb][1] = b.w;
        }
#pragma unroll
        for (int ma = 0; ma < 2; ma++) {
            int r = wm * 32 + ma * 16 + gp;
            const __nv_bfloat16* p0 = sAhi + r * ASTR_F + k + tg * 2;
            const __nv_bfloat16* p1 = sAlo + r * ASTR_F + k + tg * 2;
            ah[ma][0] = *(uint32_t*)(p0);
            ah[ma][1] = *(uint32_t*)(p0 + 8 * ASTR_F);
            ah[ma][2] = *(uint32_t*)(p0 + 8);
            ah[ma][3] = *(uint32_t*)(p0 + 8 * ASTR_F + 8);
            al[ma][0] = *(uint32_t*)(p1);
            al[ma][1] = *(uint32_t*)(p1 + 8 * ASTR_F);
            al[ma][2] = *(uint32_t*)(p1 + 8);
            al[ma][3] = *(uint32_t*)(p1 + 8 * ASTR_F + 8);
        }
#pragma unroll
        for (int ma = 0; ma < 2; ma++)
#pragma unroll
            for (int nb = 0; nb < 6; nb++) {
                mma_bf16(acc[ma][nb], ah[ma], bh[nb]);
                mma_bf16(acc[ma][nb], al[ma], bh[nb]);
                mma_bf16(acc[ma][nb], ah[ma], bl[nb]);
            }
    }

#pragma unroll
    for (int ma = 0; ma < 2; ma++) {
        int r0 = n0 + wm * 32 + ma * 16 + gp;
#pragma unroll
        for (int half = 0; half < 2; half++) {
            int r = r0 + half * 8;
            if (r < nNodes) {
#pragma unroll
                for (int nb = 0; nb < 6; nb++) {
                    int col = wn * 48 + nb * 8 + tg * 2;
                    float2 v;
                    v.x = acc[ma][nb][half * 2 + 0] + bf[col];
                    v.y = acc[ma][nb][half * 2 + 1] + bf[col + 1];
                    *(float2*)(&out[r * 96 + col]) = v;
                }
            }
        }
    }
}

// ---------------- kernel 3.5: BN stats over fused output ------------------
__global__ __launch_bounds__(384) void k_stats(const float* __restrict__ out, int nNodes)
{
    __shared__ float ss[FF], sq[FF];
    int t = threadIdx.x;
    int c = t % FF, g = t / FF;
    if (t < FF) { ss[t] = 0.f; sq[t] = 0.f; }
    __syncthreads();
    float a = 0.f, b = 0.f;
    for (int r = blockIdx.x * 4 + g; r < nNodes; r += gridDim.x * 4) {
        float v = out[r * FF + c];
        a += v; b += v * v;
    }
    atomicAdd(&ss[c], a);
    atomicAdd(&sq[c], b);
    __syncthreads();
    if (t < FF) {
        atomicAdd(&g_sum[t], ss[t]);
        atomicAdd(&g_sq[t], sq[t]);
    }
}

// ---------------- kernel 4: BatchNorm + exact GELU (in-place, float4) -----
__global__ __launch_bounds__(256) void k_bn(
    float* __restrict__ out, const float* __restrict__ gamma,
    const float* __restrict__ beta, int nNodes)
{
    __shared__ float sscale[FF], sshift[FF];
    if (threadIdx.x < FF) {
        int f = threadIdx.x;
        float invN = 1.0f / (float)nNodes;
        float mean = g_sum[f] * invN;
        float var = g_sq[f] * invN - mean * mean;
        float rs = rsqrtf(var + 1e-5f);
        float sc = rs * gamma[f];
        sscale[f] = sc;
        sshift[f] = beta[f] - mean * sc;
    }
    __syncthreads();
    int total4 = nNodes * (FF / 4);
    int idx = blockIdx.x * blockDim.x + threadIdx.x;
    int stride = gridDim.x * blockDim.x;
    for (int i = idx; i < total4; i += stride) {
        int f4 = (i % 24) * 4;
        float4 v = ((float4*)out)[i];
        float r[4] = {v.x, v.y, v.z, v.w};
#pragma unroll
        for (int j = 0; j < 4; j++) {
            float y = r[j] * sscale[f4 + j] + sshift[f4 + j];
            r[j] = 0.5f * y * (1.0f + erff(y * 0.70710678118654752f));
        }
        ((float4*)out)[i] = make_float4(r[0], r[1], r[2], r[3]);
    }
}

// ---------------- launch ----------------
extern "C" void kernel_launch(void* const* d_in, const int* in_sizes, int n_in,
                              void* d_out, int out_size)
{
    const float* x      = (const float*)d_in[0];
    const float* B      = (const float*)d_in[1];
    const float* Wp     = (const float*)d_in[2];
    const float* bp     = (const float*)d_in[3];
    const float* Wf     = (const float*)d_in[4];
    const float* bf     = (const float*)d_in[5];
    const float* gamma  = (const float*)d_in[6];
    const float* beta   = (const float*)d_in[7];
    const void* ei      = d_in[8];

    int nNodes = in_sizes[0] / 3;
    int E = in_sizes[8] / 2;
    int nTiles = (nNodes + EM - 1) / EM;
    int nScanBlocks = (nNodes + 255) / 256;

    const int smem_embed = EM * ASTR_E * 2 * 2;   // 69,632 B
    const int smem_fuse  = EM * ASTR_F * 2 * 2;   // 102,400 B
    cudaFuncSetAttribute(k_embed, cudaFuncAttributeMaxDynamicSharedMemorySize, smem_embed);
    cudaFuncSetAttribute(k_fuse,  cudaFuncAttributeMaxDynamicSharedMemorySize, smem_fuse);

    k_zero<<<256, 256>>>(nNodes);
    k_prepB<<<(16 * 12 * 32 + 255) / 256, 256>>>(Wp, Wf);
    // CSR build (overlaps conceptually with embed; stream order fine)
    k_hist<<<(E + 255) / 256, 256>>>(ei, E);
    k_s1<<<nScanBlocks, 256>>>(nNodes);
    k_s2<<<1, 256>>>(nScanBlocks);
    k_s3<<<nScanBlocks, 256>>>(nNodes);
    k_fill<<<(E + 255) / 256, 256>>>(ei, E);
    k_embed<<<nTiles, 256, smem_embed>>>(x, B, bp, nNodes);
    k_gather<<<(nNodes * 32 + 255) / 256, 256>>>(nNodes);
    k_fuse<<<nTiles, 256, smem_fuse>>>(bf, (float*)d_out, nNodes);
    k_stats<<<256, 384>>>((const float*)d_out, nNodes);
    {
        int total4 = nNodes * (FF / 4);
        k_bn<<<(total4 + 1023) / 1024, 256>>>((float*)d_out, gamma, beta, nNodes);
    }
}